// round 1
// baseline (speedup 1.0000x reference)
#include <cuda_runtime.h>

// DCT_26688926778120
// x: (B=8, C=3, T=32, H=256, W=256) fp32
// out: (B, T, 1024, 8, 8) fp32  ==  D @ gray_block @ D^T per 8x8 block
//
// One thread per 8x8 output block. Grayscale fused at load.
// Pure HBM-streaming kernel: 805 MB in + 64 MB out.

__global__ __launch_bounds__(256)
void dct_kernel(const float* __restrict__ x, float* __restrict__ out)
{
    // Unnormalized DCT-II matrix D[k][n] = 2*cos(pi*(2n+1)*k/16)
    const float D[8][8] = {
        { 2.0f,             2.0f,             2.0f,             2.0f,
          2.0f,             2.0f,             2.0f,             2.0f            },
        { 1.96157056080646f, 1.66293922460509f, 1.11114046603920f, 0.39018064403226f,
         -0.39018064403226f,-1.11114046603920f,-1.66293922460509f,-1.96157056080646f},
        { 1.84775906502257f, 0.76536686473018f,-0.76536686473018f,-1.84775906502257f,
         -1.84775906502257f,-0.76536686473018f, 0.76536686473018f, 1.84775906502257f},
        { 1.66293922460509f,-0.39018064403226f,-1.96157056080646f,-1.11114046603920f,
          1.11114046603920f, 1.96157056080646f, 0.39018064403226f,-1.66293922460509f},
        { 1.41421356237310f,-1.41421356237310f,-1.41421356237310f, 1.41421356237310f,
          1.41421356237310f,-1.41421356237310f,-1.41421356237310f, 1.41421356237310f},
        { 1.11114046603920f,-1.96157056080646f, 0.39018064403226f, 1.66293922460509f,
         -1.66293922460509f,-0.39018064403226f, 1.96157056080646f,-1.11114046603920f},
        { 0.76536686473018f,-1.84775906502257f, 1.84775906502257f,-0.76536686473018f,
         -0.76536686473018f, 1.84775906502257f,-1.84775906502257f, 0.76536686473018f},
        { 0.39018064403226f,-1.11114046603920f, 1.66293922460509f,-1.96157056080646f,
          1.96157056080646f,-1.66293922460509f, 1.11114046603920f,-0.39018064403226f}
    };

    const float WR = 0.2989f, WG = 0.587f, WB = 0.114f;

    unsigned tid = blockIdx.x * 256u + threadIdx.x;   // [0, 262144)
    unsigned wbi = tid & 31u;          // block col (fastest -> coalesced)
    unsigned hbi = (tid >> 5) & 31u;   // block row
    unsigned tt  = (tid >> 10) & 31u;  // time
    unsigned bb  = tid >> 15;          // batch

    const size_t plane   = 256u * 256u;      // 65536
    const size_t cstride = 32u * plane;      // 2097152 elements between channels

    const float* p0 = x + ((size_t)bb * 3u * 32u + tt) * plane
                        + (size_t)hbi * 8u * 256u + (size_t)wbi * 8u;

    float acc[8][8];
#pragma unroll
    for (int k = 0; k < 8; ++k)
#pragma unroll
        for (int l = 0; l < 8; ++l) acc[k][l] = 0.0f;

#pragma unroll
    for (int n = 0; n < 8; ++n) {
        const float* rp = p0 + (size_t)n * 256u;
        float4 ra = *(const float4*)(rp);
        float4 rb = *(const float4*)(rp + 4);
        float4 ga = *(const float4*)(rp + cstride);
        float4 gb = *(const float4*)(rp + cstride + 4);
        float4 ba = *(const float4*)(rp + 2u * cstride);
        float4 bc = *(const float4*)(rp + 2u * cstride + 4);

        float g[8];
        g[0] = WR * ra.x + WG * ga.x + WB * ba.x;
        g[1] = WR * ra.y + WG * ga.y + WB * ba.y;
        g[2] = WR * ra.z + WG * ga.z + WB * ba.z;
        g[3] = WR * ra.w + WG * ga.w + WB * ba.w;
        g[4] = WR * rb.x + WG * gb.x + WB * bc.x;
        g[5] = WR * rb.y + WG * gb.y + WB * bc.y;
        g[6] = WR * rb.z + WG * gb.z + WB * bc.z;
        g[7] = WR * rb.w + WG * gb.w + WB * bc.w;

        // Row DCT: y[l] = sum_m g[m] * D[l][m]
        float y[8];
#pragma unroll
        for (int l = 0; l < 8; ++l) {
            float s = D[l][0] * g[0];
#pragma unroll
            for (int m = 1; m < 8; ++m) s += D[l][m] * g[m];
            y[l] = s;
        }

        // Column accumulate: acc[k][l] += D[k][n] * y[l]
#pragma unroll
        for (int k = 0; k < 8; ++k) {
            float dk = D[k][n];
#pragma unroll
            for (int l = 0; l < 8; ++l) acc[k][l] += dk * y[l];
        }
    }

    // Output: out[((b*32+t)*1024 + hbi*32 + wbi)*64 + k*8 + l] == out[tid*64 + ...]
    float4* op = (float4*)(out + (size_t)tid * 64u);
#pragma unroll
    for (int k = 0; k < 8; ++k) {
        op[2 * k]     = make_float4(acc[k][0], acc[k][1], acc[k][2], acc[k][3]);
        op[2 * k + 1] = make_float4(acc[k][4], acc[k][5], acc[k][6], acc[k][7]);
    }
}

extern "C" void kernel_launch(void* const* d_in, const int* in_sizes, int n_in,
                              void* d_out, int out_size)
{
    const float* x = (const float*)d_in[0];
    float* out = (float*)d_out;
    // 262,144 blocks total, one thread each
    dct_kernel<<<1024, 256>>>(x, out);
}